// round 10
// baseline (speedup 1.0000x reference)
#include <cuda_runtime.h>
#include <cuda_fp16.h>
#include <math.h>
#include <stdint.h>

#define BQ 128
#define NQ 512
#define HQ 128
#define M2 65536

// ---------------- scratch (allocation-free rule) ----------------
// Packed fp16 hi/lo operand words: each uint32 = half2 (k, k+1)
__device__ uint32_t g_Aph[(size_t)BQ * 256 * 512];   // A K-major: [b][kp][n]
__device__ uint32_t g_Apl[(size_t)BQ * 256 * 512];
__device__ uint32_t g_hKh[(size_t)BQ * 256 * 128];   // h K-major: [b][kp][h]
__device__ uint32_t g_hKl[(size_t)BQ * 256 * 128];
__device__ uint32_t g_aMh[(size_t)M2 * 64];          // a M-major: [i][jp]
__device__ uint32_t g_aMl[(size_t)M2 * 64];
__device__ uint32_t g_rMh[(size_t)M2 * 64];          // rh M-major
__device__ uint32_t g_rMl[(size_t)M2 * 64];
__device__ uint32_t g_hMh[(size_t)M2 * 64];          // h M-major
__device__ uint32_t g_hMl[(size_t)M2 * 64];
__device__ float    g_z [(size_t)M2 * HQ];
__device__ float    g_h0[(size_t)M2 * HQ];
__device__ float    g_h1[(size_t)M2 * HQ];
__device__ uint32_t g_Wh[12 * (size_t)HQ * HQ / 2];  // weights packed M-major
// [0,1]=wz(hi,lo) [2,3]=uz [4,5]=wr [6,7]=ur [8,9]=w [10,11]=u ; 8192 words each

// ---------------- helpers ----------------
__device__ __forceinline__ void cpa16(uint32_t dst, const void* src) {
    asm volatile("cp.async.cg.shared.global [%0], [%1], 16;" :: "r"(dst), "l"(src));
}
#define CP_COMMIT() asm volatile("cp.async.commit_group;" ::: "memory")
#define CP_WAIT1()  asm volatile("cp.async.wait_group 1;" ::: "memory")
#define CP_WAIT0()  asm volatile("cp.async.wait_group 0;" ::: "memory")

__device__ __forceinline__ uint32_t smem_u32(const void* p) {
    uint32_t a;
    asm("{ .reg .u64 t; cvta.to.shared.u64 t, %1; cvt.u32.u64 %0, t; }" : "=r"(a) : "l"(p));
    return a;
}
__device__ __forceinline__ void hsplit2(float x, float y, uint32_t& hi, uint32_t& lo) {
    __half hx = __float2half_rn(x);
    __half hy = __float2half_rn(y);
    __half lx = __float2half_rn(x - __half2float(hx));
    __half ly = __float2half_rn(y - __half2float(hy));
    __half2 H = __halves2half2(hx, hy);
    __half2 L = __halves2half2(lx, ly);
    hi = *reinterpret_cast<uint32_t*>(&H);
    lo = *reinterpret_cast<uint32_t*>(&L);
}
__device__ __forceinline__ void mma16(float* c, const uint32_t* a, const uint32_t* b) {
    asm volatile(
        "mma.sync.aligned.m16n8k16.row.col.f32.f16.f16.f32 "
        "{%0,%1,%2,%3}, {%4,%5,%6,%7}, {%8,%9}, {%0,%1,%2,%3};"
        : "+f"(c[0]), "+f"(c[1]), "+f"(c[2]), "+f"(c[3])
        : "r"(a[0]), "r"(a[1]), "r"(a[2]), "r"(a[3]), "r"(b[0]), "r"(b[1]));
}
#define LDSM4(r0, r1, r2, r3, a)                                               \
    asm volatile("ldmatrix.sync.aligned.m8n8.x4.shared.b16 {%0,%1,%2,%3}, [%4];" \
                 : "=r"(r0), "=r"(r1), "=r"(r2), "=r"(r3) : "r"(a))

// ---------------------------------------------------------------------------
// M-major split: raw fp32 row-stream -> packed half2 k-pair words (hi, lo)
// (used for weights and initial hidden M-major form)
// ---------------------------------------------------------------------------
__global__ __launch_bounds__(256)
void k_splith(const float* __restrict__ s, uint32_t* __restrict__ hi,
              uint32_t* __restrict__ lo, int n4)
{
    int i = blockIdx.x * blockDim.x + threadIdx.x;
    if (i >= n4) return;
    float4 v = reinterpret_cast<const float4*>(s)[i];
    uint32_t h0, l0, h1, l1;
    hsplit2(v.x, v.y, h0, l0);
    hsplit2(v.z, v.w, h1, l1);
    uint2 H; H.x = h0; H.y = h1;
    uint2 L; L.x = l0; L.y = l1;
    reinterpret_cast<uint2*>(hi)[i] = H;
    reinterpret_cast<uint2*>(lo)[i] = L;
}

// ---------------------------------------------------------------------------
// K-major split: pack across row pairs. SH=7: rows of 512 floats (A);
// SH=5: rows of 128 floats (h). Packed row bk <- raw rows 2bk, 2bk+1.
// ---------------------------------------------------------------------------
template<int SH>
__global__ __launch_bounds__(256)
void k_splitK(const float* __restrict__ s, uint32_t* __restrict__ hi,
              uint32_t* __restrict__ lo)
{
    const int W4 = 1 << SH;                       // uint4 per packed row
    size_t tid = (size_t)blockIdx.x * 256 + threadIdx.x;
    size_t c = tid & (W4 - 1), bk = tid >> SH;
    const float* r0 = s + bk * (size_t)(8 << SH) + c * 4;
    const float* r1 = r0 + (4 << SH);
    float4 v0 = *reinterpret_cast<const float4*>(r0);
    float4 v1 = *reinterpret_cast<const float4*>(r1);
    uint4 H, L;
    hsplit2(v0.x, v1.x, H.x, L.x);
    hsplit2(v0.y, v1.y, H.y, L.y);
    hsplit2(v0.z, v1.z, H.z, L.z);
    hsplit2(v0.w, v1.w, H.w, L.w);
    reinterpret_cast<uint4*>(hi)[bk * W4 + c] = H;
    reinterpret_cast<uint4*>(lo)[bk * W4 + c] = L;
}

// ---------------------------------------------------------------------------
// a-GEMM: a[b,n,h] = sum_m A[b,m,n]*h[b,m,h] + bias[h]; writes a packed M-major.
// All operands pre-packed fp16; pure cp.async -> LDS -> MMA.
// K-major smem [kp][i] stride 136 words, K-chunk 16 (8 kp rows), C=32, 2-stage.
// smem 34816 B, 2 CTA/SM.
// ---------------------------------------------------------------------------
#define AT_W 1088            // 8*136
#define AS_W 4352            // 4 tiles
__global__ __launch_bounds__(256, 2)
void k_mma_a(const uint32_t* __restrict__ Aph, const uint32_t* __restrict__ Apl,
             const uint32_t* __restrict__ Hh, const uint32_t* __restrict__ Hl,
             const float* __restrict__ bias,
             uint32_t* __restrict__ aMh, uint32_t* __restrict__ aMl)
{
    extern __shared__ uint32_t su[];
    const uint32_t sb = smem_u32(su);
    const int t = threadIdx.x, lane = t & 31, wid = t >> 5;
    const int wi = wid & 1, wj = wid >> 1;
    const int g = lane >> 2, tq = lane & 3;
    const int b = blockIdx.y, n0 = blockIdx.x * 128;
    const int kp = t >> 5, c4 = t & 31;

    float acc[4][4][4];
#pragma unroll
    for (int a_ = 0; a_ < 4; a_++)
#pragma unroll
        for (int b_ = 0; b_ < 4; b_++)
#pragma unroll
            for (int c_ = 0; c_ < 4; c_++) acc[a_][b_][c_] = 0.f;

    const int C = 32;
#define A_CPA(cc, st)                                                          \
    {                                                                          \
        const uint32_t d0 = sb + (uint32_t)(st) * AS_W * 4                     \
                               + (uint32_t)(kp * 136 + c4 * 4) * 4;            \
        const size_t rb_ = (size_t)b * 256 + (cc) * 8 + kp;                    \
        cpa16(d0,              Aph + rb_ * 512 + n0 + c4 * 4);                 \
        cpa16(d0 + AT_W * 4,   Apl + rb_ * 512 + n0 + c4 * 4);                 \
        cpa16(d0 + 2*AT_W*4,   Hh  + rb_ * 128 + c4 * 4);                      \
        cpa16(d0 + 3*AT_W*4,   Hl  + rb_ * 128 + c4 * 4);                      \
        CP_COMMIT();                                                           \
    }

    A_CPA(0, 0);
    for (int c = 0; c < C; c++) {
        const int sc = c & 1;
        if (c + 1 < C) { A_CPA(c + 1, (c + 1) & 1); CP_WAIT1(); }
        else           { CP_WAIT0(); }
        __syncthreads();
        const uint32_t* Xh = su + sc * AS_W;
        const uint32_t* Xl = Xh + AT_W;
        const uint32_t* Wh = Xh + 2 * AT_W;
        const uint32_t* Wl = Xh + 3 * AT_W;
        uint32_t ah[4][4], al[4][4], bh[4][2], bl[4][2];
#pragma unroll
        for (int mf = 0; mf < 4; mf++) {
            const int r = wi * 64 + mf * 16 + g;
            ah[mf][0] = Xh[tq * 136 + r];
            ah[mf][1] = Xh[tq * 136 + r + 8];
            ah[mf][2] = Xh[(tq + 4) * 136 + r];
            ah[mf][3] = Xh[(tq + 4) * 136 + r + 8];
            al[mf][0] = Xl[tq * 136 + r];
            al[mf][1] = Xl[tq * 136 + r + 8];
            al[mf][2] = Xl[(tq + 4) * 136 + r];
            al[mf][3] = Xl[(tq + 4) * 136 + r + 8];
        }
#pragma unroll
        for (int nf = 0; nf < 4; nf++) {
            const int cj = wj * 32 + nf * 8 + g;
            bh[nf][0] = Wh[tq * 136 + cj];
            bh[nf][1] = Wh[(tq + 4) * 136 + cj];
            bl[nf][0] = Wl[tq * 136 + cj];
            bl[nf][1] = Wl[(tq + 4) * 136 + cj];
        }
#pragma unroll
        for (int nf = 0; nf < 4; nf++)
#pragma unroll
            for (int mf = 0; mf < 4; mf++) mma16(acc[mf][nf], ah[mf], bh[nf]);
#pragma unroll
        for (int nf = 0; nf < 4; nf++)
#pragma unroll
            for (int mf = 0; mf < 4; mf++) mma16(acc[mf][nf], al[mf], bh[nf]);
#pragma unroll
        for (int nf = 0; nf < 4; nf++)
#pragma unroll
            for (int mf = 0; mf < 4; mf++) mma16(acc[mf][nf], ah[mf], bl[nf]);
        __syncthreads();
    }
#undef A_CPA

#pragma unroll
    for (int mf = 0; mf < 4; mf++) {
#pragma unroll
        for (int h2 = 0; h2 < 2; h2++) {
            const int i = n0 + wi * 64 + mf * 16 + g + h2 * 8;
            const size_t rb = ((size_t)b * NQ + i) * 64;
#pragma unroll
            for (int nf = 0; nf < 4; nf++) {
                const int j  = wj * 32 + nf * 8 + 2 * tq;
                const int jp = wj * 16 + nf * 4 + tq;
                const float2 bb = *reinterpret_cast<const float2*>(bias + j);
                float v0 = acc[mf][nf][h2 * 2 + 0] + bb.x;
                float v1 = acc[mf][nf][h2 * 2 + 1] + bb.y;
                uint32_t H, L;
                hsplit2(v0, v1, H, L);
                aMh[rb + jp] = H;
                aMl[rb + jp] = L;
            }
        }
    }
}

// ---------------------------------------------------------------------------
// Fused z+r: [z|r] = a@[wz|wr]^T + h@[uz|ur]^T (+biases)
// CTA 64 rows x 256 cols, warp tile 64x32. M-major packed smem stride 12.
// cp.async everything; LDSM fragments. 2-stage; smem 61440 B; 2 CTA/SM.
// z -> raw; rh -> packed M-major hi/lo.
// ---------------------------------------------------------------------------
#define ZT_X 768             // 64*12
#define ZT_W 3072            // 256*12
#define ZS_W 7680
__global__ __launch_bounds__(256, 2)
void k_zr(const uint32_t* __restrict__ aMh, const uint32_t* __restrict__ aMl,
          const uint32_t* __restrict__ hMh, const uint32_t* __restrict__ hMl,
          const uint32_t* __restrict__ Wsp,
          const float* __restrict__ b_wz, const float* __restrict__ b_uz,
          const float* __restrict__ b_wr, const float* __restrict__ b_ur,
          const float* __restrict__ hraw,
          float* __restrict__ zout, uint32_t* __restrict__ rMh,
          uint32_t* __restrict__ rMl)
{
    extern __shared__ uint32_t su[];
    const uint32_t sb = smem_u32(su);
    const int t = threadIdx.x, lane = t & 31, wj = t >> 5;
    const int g = lane >> 2, tq = lane & 3;
    const int i0 = blockIdx.x * 64;
    const int SW = HQ * HQ / 2;
    const int xo = ((lane & 7) + ((lane >> 3) & 1) * 8) * 12 + ((lane >> 4) & 1) * 4;
    const int wo = ((lane & 7) + ((lane >> 4) & 1) * 8) * 12 + ((lane >> 3) & 1) * 4;

    float acc[4][4][4];
#pragma unroll
    for (int a_ = 0; a_ < 4; a_++)
#pragma unroll
        for (int b_ = 0; b_ < 4; b_++)
#pragma unroll
            for (int c_ = 0; c_ < 4; c_++) acc[a_][b_][c_] = 0.f;

    const int C = 16;
#define Z_CPA(cc, st)                                                          \
    {                                                                          \
        const int half = (cc) >> 3;                                            \
        const int kw = ((cc) & 7) * 8;                                         \
        const uint32_t* xh_ = (half ? hMh : aMh) + (size_t)i0 * 64 + kw;       \
        const uint32_t* xl_ = (half ? hMl : aMl) + (size_t)i0 * 64 + kw;       \
        const uint32_t s0 = sb + (uint32_t)(st) * ZS_W * 4;                    \
        {                                                                      \
            const int tt = t & 127, row = tt >> 1, f4 = tt & 1;                \
            cpa16(s0 + (uint32_t)((t < 128 ? 0 : ZT_X) + row * 12 + f4 * 4)*4, \
                  (t < 128 ? xh_ : xl_) + (size_t)row * 64 + f4 * 4);          \
        }                                                                      \
        const uint32_t* w1h = Wsp + (half ? 2 : 0) * SW + kw;                  \
        const uint32_t* w1l = Wsp + (half ? 3 : 1) * SW + kw;                  \
        const uint32_t* w2h = Wsp + (half ? 6 : 4) * SW + kw;                  \
        const uint32_t* w2l = Wsp + (half ? 7 : 5) * SW + kw;                  \
        _Pragma("unroll")                                                      \
        for (int p = 0; p < 2; p++) {                                          \
            const int idx = t + p * 256;                                       \
            const int row = idx >> 1, f4 = idx & 1;                            \
            const uint32_t off = (uint32_t)(row * 12 + f4 * 4) * 4;            \
            const uint32_t* sh = (row < 128) ? (w1h + (size_t)row * 64)        \
                                             : (w2h + (size_t)(row - 128) * 64); \
            const uint32_t* sl = (row < 128) ? (w1l + (size_t)row * 64)        \
                                             : (w2l + (size_t)(row - 128) * 64); \
            cpa16(s0 + 2 * ZT_X * 4 + off,            sh + f4 * 4);            \
            cpa16(s0 + (2 * ZT_X + ZT_W) * 4 + off,   sl + f4 * 4);            \
        }                                                                      \
        CP_COMMIT();                                                           \
    }

    Z_CPA(0, 0);
    for (int c = 0; c < C; c++) {
        const int sc = c & 1;
        if (c + 1 < C) { Z_CPA(c + 1, (c + 1) & 1); CP_WAIT1(); }
        else           { CP_WAIT0(); }
        __syncthreads();
        const uint32_t xb = sb + (uint32_t)sc * ZS_W * 4;
        const uint32_t wb = xb + 2 * ZT_X * 4;
        uint32_t ah[4][4], al[4][4], bh[4][2], bl[4][2];
#pragma unroll
        for (int mf = 0; mf < 4; mf++) {
            const uint32_t axy = xb + (uint32_t)(mf * 16 * 12 + xo) * 4;
            LDSM4(ah[mf][0], ah[mf][1], ah[mf][2], ah[mf][3], axy);
            LDSM4(al[mf][0], al[mf][1], al[mf][2], al[mf][3], axy + ZT_X * 4);
        }
#pragma unroll
        for (int p = 0; p < 2; p++) {
            const uint32_t bxy = wb + (uint32_t)((wj * 32 + p * 16) * 12 + wo) * 4;
            LDSM4(bh[2*p][0], bh[2*p][1], bh[2*p+1][0], bh[2*p+1][1], bxy);
            LDSM4(bl[2*p][0], bl[2*p][1], bl[2*p+1][0], bl[2*p+1][1], bxy + ZT_W * 4);
        }
#pragma unroll
        for (int nf = 0; nf < 4; nf++)
#pragma unroll
            for (int mf = 0; mf < 4; mf++) mma16(acc[mf][nf], ah[mf], bh[nf]);
#pragma unroll
        for (int nf = 0; nf < 4; nf++)
#pragma unroll
            for (int mf = 0; mf < 4; mf++) mma16(acc[mf][nf], al[mf], bh[nf]);
#pragma unroll
        for (int nf = 0; nf < 4; nf++)
#pragma unroll
            for (int mf = 0; mf < 4; mf++) mma16(acc[mf][nf], ah[mf], bl[nf]);
        __syncthreads();
    }
#undef Z_CPA

#pragma unroll
    for (int mf = 0; mf < 4; mf++) {
#pragma unroll
        for (int h2 = 0; h2 < 2; h2++) {
            const int i = i0 + mf * 16 + g + h2 * 8;
            const size_t rb = (size_t)i * HQ;
#pragma unroll
            for (int nf = 0; nf < 4; nf++) {
                const int j = wj * 32 + nf * 8 + 2 * tq;
                if (wj < 4) {
                    const float2 bb1 = *reinterpret_cast<const float2*>(b_wz + j);
                    const float2 bb2 = *reinterpret_cast<const float2*>(b_uz + j);
                    float v0 = acc[mf][nf][h2 * 2 + 0] + bb1.x + bb2.x;
                    float v1 = acc[mf][nf][h2 * 2 + 1] + bb1.y + bb2.y;
                    float2 o;
                    o.x = 1.f / (1.f + __expf(-v0));
                    o.y = 1.f / (1.f + __expf(-v1));
                    *reinterpret_cast<float2*>(zout + rb + j) = o;
                } else {
                    const int jj = j - 128;
                    const int jjp = (wj - 4) * 16 + nf * 4 + tq;
                    const float2 bb1 = *reinterpret_cast<const float2*>(b_wr + jj);
                    const float2 bb2 = *reinterpret_cast<const float2*>(b_ur + jj);
                    float v0 = acc[mf][nf][h2 * 2 + 0] + bb1.x + bb2.x;
                    float v1 = acc[mf][nf][h2 * 2 + 1] + bb1.y + bb2.y;
                    const float2 hv = *reinterpret_cast<const float2*>(hraw + rb + jj);
                    float r0 = hv.x * (1.f / (1.f + __expf(-v0)));
                    float r1 = hv.y * (1.f / (1.f + __expf(-v1)));
                    uint32_t H, L;
                    hsplit2(r0, r1, H, L);
                    rMh[(size_t)i * 64 + jjp] = H;
                    rMl[(size_t)i * 64 + jjp] = L;
                }
            }
        }
    }
}

// ---------------------------------------------------------------------------
// c-gate: D = a@w^T + rh@u^T (+b); h' = (1-z)h + z tanh(D)
// CTA 128x128, M-major packed stride 12, K-chunk 16, C=16, 2-stage.
// smem 49152 B; 2 CTA/SM. Writes raw h' + packed M-major hi/lo.
// ---------------------------------------------------------------------------
#define GT_W 1536
#define GS_W 6144
__global__ __launch_bounds__(256, 2)
void k_cgate(const uint32_t* __restrict__ aMh, const uint32_t* __restrict__ aMl,
             const uint32_t* __restrict__ rMh, const uint32_t* __restrict__ rMl,
             const uint32_t* __restrict__ Wsp,
             const float* __restrict__ b1, const float* __restrict__ b2,
             const float* __restrict__ hraw, const float* __restrict__ zp,
             float* __restrict__ outp, uint32_t* __restrict__ hMh,
             uint32_t* __restrict__ hMl)
{
    extern __shared__ uint32_t su[];
    const uint32_t sb = smem_u32(su);
    const int t = threadIdx.x, lane = t & 31, wid = t >> 5;
    const int wi = wid & 1, wj = wid >> 1;
    const int g = lane >> 2, tq = lane & 3;
    const int i0 = blockIdx.x * 128;
    const int SW = HQ * HQ / 2;
    const int xo = ((lane & 7) + ((lane >> 3) & 1) * 8) * 12 + ((lane >> 4) & 1) * 4;
    const int wo = ((lane & 7) + ((lane >> 4) & 1) * 8) * 12 + ((lane >> 3) & 1) * 4;

    float acc[4][4][4];
#pragma unroll
    for (int a_ = 0; a_ < 4; a_++)
#pragma unroll
        for (int b_ = 0; b_ < 4; b_++)
#pragma unroll
            for (int c_ = 0; c_ < 4; c_++) acc[a_][b_][c_] = 0.f;

    const int C = 16;
#define G_CPA(cc, st)                                                          \
    {                                                                          \
        const int gg = (cc) >> 3;                                              \
        const int kw = ((cc) & 7) * 8;                                         \
        const uint32_t* xh_ = (gg ? rMh : aMh) + (size_t)i0 * 64 + kw;         \
        const uint32_t* xl_ = (gg ? rMl : aMl) + (size_t)i0 * 64 + kw;         \
        const uint32_t* wh_ = Wsp + (gg ? 10 : 8) * SW + kw;                   \
        const uint32_t* wl_ = Wsp + (gg ? 11 : 9) * SW + kw;                   \
        const uint32_t s0 = sb + (uint32_t)(st) * GS_W * 4;                    \
        _Pragma("unroll")                                                      \
        for (int p = 0; p < 2; p++) {                                          \
            const int slot = t + p * 256;                                      \
            const int tile = slot >> 8, rs = slot & 255;                       \
            const int row = rs >> 1, f4 = rs & 1;                              \
            const uint32_t off = (uint32_t)(row * 12 + f4 * 4) * 4;            \
            cpa16(s0 + (uint32_t)tile * GT_W * 4 + off,                        \
                  (tile ? xl_ : xh_) + (size_t)row * 64 + f4 * 4);             \
            cpa16(s0 + (uint32_t)(2 + tile) * GT_W * 4 + off,                  \
                  (tile ? wl_ : wh_) + (size_t)row * 64 + f4 * 4);             \
        }                                                                      \
        CP_COMMIT();                                                           \
    }

    G_CPA(0, 0);
    for (int c = 0; c < C; c++) {
        const int sc = c & 1;
        if (c + 1 < C) { G_CPA(c + 1, (c + 1) & 1); CP_WAIT1(); }
        else           { CP_WAIT0(); }
        __syncthreads();
        const uint32_t xb = sb + (uint32_t)sc * GS_W * 4;
        const uint32_t wb = xb + 2 * GT_W * 4;
        uint32_t ah[4][4], al[4][4], bh[4][2], bl[4][2];
#pragma unroll
        for (int mf = 0; mf < 4; mf++) {
            const uint32_t axy = xb + (uint32_t)((wi * 64 + mf * 16) * 12 + xo) * 4;
            LDSM4(ah[mf][0], ah[mf][1], ah[mf][2], ah[mf][3], axy);
            LDSM4(al[mf][0], al[mf][1], al[mf][2], al[mf][3], axy + GT_W * 4);
        }
#pragma unroll
        for (int p = 0; p < 2; p++) {
            const uint32_t bxy = wb + (uint32_t)((wj * 32 + p * 16) * 12 + wo) * 4;
            LDSM4(bh[2*p][0], bh[2*p][1], bh[2*p+1][0], bh[2*p+1][1], bxy);
            LDSM4(bl[2*p][0], bl[2*p][1], bl[2*p+1][0], bl[2*p+1][1], bxy + GT_W * 4);
        }
#pragma unroll
        for (int nf = 0; nf < 4; nf++)
#pragma unroll
            for (int mf = 0; mf < 4; mf++) mma16(acc[mf][nf], ah[mf], bh[nf]);
#pragma unroll
        for (int nf = 0; nf < 4; nf++)
#pragma unroll
            for (int mf = 0; mf < 4; mf++) mma16(acc[mf][nf], al[mf], bh[nf]);
#pragma unroll
        for (int nf = 0; nf < 4; nf++)
#pragma unroll
            for (int mf = 0; mf < 4; mf++) mma16(acc[mf][nf], ah[mf], bl[nf]);
        __syncthreads();
    }
#undef G_CPA

#pragma unroll
    for (int mf = 0; mf < 4; mf++) {
#pragma unroll
        for (int h2 = 0; h2 < 2; h2++) {
            const int i = i0 + wi * 64 + mf * 16 + g + h2 * 8;
            const size_t rb = (size_t)i * HQ;
#pragma unroll
            for (int nf = 0; nf < 4; nf++) {
                const int j  = wj * 32 + nf * 8 + 2 * tq;
                const int jp = wj * 16 + nf * 4 + tq;
                const float2 bb1 = *reinterpret_cast<const float2*>(b1 + j);
                const float2 bb2 = *reinterpret_cast<const float2*>(b2 + j);
                float v0 = acc[mf][nf][h2 * 2 + 0] + bb1.x + bb2.x;
                float v1 = acc[mf][nf][h2 * 2 + 1] + bb1.y + bb2.y;
                const float2 hv = *reinterpret_cast<const float2*>(hraw + rb + j);
                const float2 zz = *reinterpret_cast<const float2*>(zp + rb + j);
                float2 o;
                o.x = (1.f - zz.x) * hv.x + zz.x * tanhf(v0);
                o.y = (1.f - zz.y) * hv.y + zz.y * tanhf(v1);
                *reinterpret_cast<float2*>(outp + rb + j) = o;
                uint32_t H, L;
                hsplit2(o.x, o.y, H, L);
                hMh[(size_t)i * 64 + jp] = H;
                hMl[(size_t)i * 64 + jp] = L;
            }
        }
    }
}

// ---------------------------------------------------------------------------
// Host launcher
// ---------------------------------------------------------------------------
extern "C" void kernel_launch(void* const* d_in, const int* in_sizes, int n_in,
                              void* d_out, int out_size)
{
    const float* A      = (const float*)d_in[0];
    const float* hidden = (const float*)d_in[1];
    const float* b_ah   = (const float*)d_in[2];
    const float* w_z    = (const float*)d_in[3];
    const float* b_wz   = (const float*)d_in[4];
    const float* u_z    = (const float*)d_in[5];
    const float* b_uz   = (const float*)d_in[6];
    const float* w_r    = (const float*)d_in[7];
    const float* b_wr   = (const float*)d_in[8];
    const float* u_r    = (const float*)d_in[9];
    const float* b_ur   = (const float*)d_in[10];
    const float* w      = (const float*)d_in[11];
    const float* b_w    = (const float*)d_in[12];
    const float* u      = (const float*)d_in[13];
    const float* b_u    = (const float*)d_in[14];
    float* out = (float*)d_out;

    uint32_t *Aph, *Apl, *hKh, *hKl, *aMh, *aMl, *rMh, *rMl, *hMh, *hMl, *Wsp;
    float *gz, *h0, *h1;
    cudaGetSymbolAddress((void**)&Aph, g_Aph);
    cudaGetSymbolAddress((void**)&Apl, g_Apl);
    cudaGetSymbolAddress((void**)&hKh, g_hKh);
    cudaGetSymbolAddress((void**)&hKl, g_hKl);
    cudaGetSymbolAddress((void**)&aMh, g_aMh);
    cudaGetSymbolAddress((void**)&aMl, g_aMl);
    cudaGetSymbolAddress((void**)&rMh, g_rMh);
    cudaGetSymbolAddress((void**)&rMl, g_rMl);
    cudaGetSymbolAddress((void**)&hMh, g_hMh);
    cudaGetSymbolAddress((void**)&hMl, g_hMl);
    cudaGetSymbolAddress((void**)&Wsp, g_Wh);
    cudaGetSymbolAddress((void**)&gz,  g_z);
    cudaGetSymbolAddress((void**)&h0,  g_h0);
    cudaGetSymbolAddress((void**)&h1,  g_h1);

    cudaFuncSetAttribute(k_mma_a, cudaFuncAttributeMaxDynamicSharedMemorySize, 34816);
    cudaFuncSetAttribute(k_zr,    cudaFuncAttributeMaxDynamicSharedMemorySize, 61440);
    cudaFuncSetAttribute(k_cgate, cudaFuncAttributeMaxDynamicSharedMemorySize, 49152);

    const int S  = HQ * HQ;
    const int SW = S / 2;
    k_splith<<<S / 1024, 256>>>(w_z, Wsp + 0 * SW,  Wsp + 1 * SW,  S / 4);
    k_splith<<<S / 1024, 256>>>(u_z, Wsp + 2 * SW,  Wsp + 3 * SW,  S / 4);
    k_splith<<<S / 1024, 256>>>(w_r, Wsp + 4 * SW,  Wsp + 5 * SW,  S / 4);
    k_splith<<<S / 1024, 256>>>(u_r, Wsp + 6 * SW,  Wsp + 7 * SW,  S / 4);
    k_splith<<<S / 1024, 256>>>(w,   Wsp + 8 * SW,  Wsp + 9 * SW,  S / 4);
    k_splith<<<S / 1024, 256>>>(u,   Wsp + 10 * SW, Wsp + 11 * SW, S / 4);

    // A K-major packed (once per launch)
    k_splitK<7><<<16384, 256>>>(A, Aph, Apl);
    // initial hidden: K-major + M-major packed
    k_splitK<5><<<4096, 256>>>(hidden, hKh, hKl);
    k_splith<<<M2 * HQ / 1024, 256>>>(hidden, hMh, hMl, M2 * HQ / 4);

    const float* hpr[4] = { hidden, h0, h1, h0 };
    float*       hnr[4] = { h0, h1, h0, out };

    for (int s = 0; s < 4; s++) {
        k_mma_a<<<dim3(4, BQ), 256, 34816>>>(Aph, Apl, hKh, hKl, b_ah, aMh, aMl);
        k_zr<<<M2 / 64, 256, 61440>>>(aMh, aMl, hMh, hMl, Wsp,
                                      b_wz, b_uz, b_wr, b_ur, hpr[s],
                                      gz, rMh, rMl);
        k_cgate<<<M2 / 128, 256, 49152>>>(aMh, aMl, rMh, rMl, Wsp,
                                          b_w, b_u, hpr[s], gz,
                                          hnr[s], hMh, hMl);
        if (s < 3) k_splitK<5><<<4096, 256>>>(hnr[s], hKh, hKl);
    }
}